// round 1
// baseline (speedup 1.0000x reference)
#include <cuda_runtime.h>
#include <math.h>

// ============================================================================
// BiDirectionalSymplecticLayer on GB300 — fp32 baseline
//
// Structure: 8 sequential gradient evaluations over a batched state of
// M = 16384 rows (rows 0..8191 = forward chain dt=+0.1, rows 8192..16383 =
// backward chain dt=-0.1). Each eval = 4 GEMMs (M,256)x(256,256) with fused
// elementwise epilogues. Second eval of each leapfrog step only needs the
// first 128 output columns of pass 4 (half GEMM).
// ============================================================================

#define D       256
#define FD      128
#define MTOT    16384
#define BHALF   8192
#define DT_MAG  0.1f

#define BM 128
#define BN 128
#define BK 16
#define NTHREADS 256

// Scratch state in device globals (allowed; no cudaMalloc anywhere)
__device__ float g_S [MTOT * D];   // state [q | p]
__device__ float g_H1[MTOT * D];   // h1 = tanh(S@W1+b1)  (needed again in pass 3)
__device__ float g_G2[MTOT * D];   // g2
__device__ float g_G1[MTOT * D];   // g1
__device__ float g_W1T[D * D];
__device__ float g_W2T[D * D];

// ----------------------------------------------------------------------------
__global__ void prep_kernel(const float* __restrict__ W1,
                            const float* __restrict__ W2) {
    int idx = blockIdx.x * blockDim.x + threadIdx.x;   // 65536 threads
    int r = idx >> 8;
    int c = idx & 255;
    g_W1T[c * D + r] = W1[idx];
    g_W2T[c * D + r] = W2[idx];
}

__global__ void init_kernel(const float* __restrict__ x) {
    int b = blockIdx.x;          // 8192
    int f = threadIdx.x;         // 128
    size_t xb = (size_t)b * 64 * 128;
    float xm  = x[xb + 32 * 128 + f];
    float xm1 = x[xb + 31 * 128 + f];
    float q = xm;
    float p = xm - xm1;
    g_S[(size_t)b * D + f]                    = q;
    g_S[(size_t)b * D + FD + f]               = p;
    g_S[(size_t)(BHALF + b) * D + f]          = q;
    g_S[(size_t)(BHALF + b) * D + FD + f]     = p;
}

__global__ void final_kernel(const float* __restrict__ x,
                             float* __restrict__ out) {
    int b = blockIdx.x;
    int f = threadIdx.x;
    size_t xb = (size_t)b * 64 * 128;
    float xm  = x[xb + 32 * 128 + f];
    float xm1 = x[xb + 31 * 128 + f];
    size_t ob = (size_t)b * 768;
    size_t sf = (size_t)b * D;               // forward chain
    size_t sb = (size_t)(BHALF + b) * D;     // backward chain
    out[ob + 0 * FD + f] = g_S[sb + f];          // q_b
    out[ob + 1 * FD + f] = g_S[sb + FD + f];     // p_b
    out[ob + 2 * FD + f] = xm;                   // q_mid
    out[ob + 3 * FD + f] = xm - xm1;             // p_mid
    out[ob + 4 * FD + f] = g_S[sf + f];          // q_f
    out[ob + 5 * FD + f] = g_S[sf + FD + f];     // p_f
}

// ----------------------------------------------------------------------------
// Fused GEMM: C = A @ B with per-mode epilogue.
//  MODE 0: A=g_S,  B=W1  -> g_H1 = tanh(acc + b1[n])
//  MODE 1: A=g_H1, B=W2  -> g_G2 = wout[n] * (1 - tanh(acc + b2[n])^2)
//  MODE 2: A=g_G2, B=g_W2T -> g_G1 = acc * (1 - g_H1^2)
//  MODE 3: A=g_G1, B=g_W1T -> leapfrog kind A: p += 0.5*dt*(-dH_q), q += dt*dH_p
//  MODE 4: A=g_G1, B=g_W1T -> leapfrog kind B (N=128 launch): p += 0.5*dt*(-dH_q)
// ----------------------------------------------------------------------------
template <int MODE>
__global__ __launch_bounds__(NTHREADS)
void gemm_kernel(const float* __restrict__ Wb,
                 const float* __restrict__ bias,
                 const float* __restrict__ wout) {
    const float* A;
    const float* B;
    if (MODE == 0)      { A = g_S;  B = Wb; }
    else if (MODE == 1) { A = g_H1; B = Wb; }
    else if (MODE == 2) { A = g_G2; B = g_W2T; }
    else                { A = g_G1; B = g_W1T; }

    __shared__ float As[BK][BM];
    __shared__ float Bs[BK][BN];

    const int tid = threadIdx.x;
    const int tx  = tid & 15;
    const int ty  = tid >> 4;
    const int m0  = blockIdx.x * BM;
    const int n0  = blockIdx.y * BN;

    // global-load mapping
    const int arow = tid >> 2;           // 0..63
    const int acol = (tid & 3) << 2;     // 0,4,8,12 (k within tile)
    const int brow = tid >> 5;           // 0..7     (k within tile)
    const int bcol = (tid & 31) << 2;    // 0..124

    const float* Ag = A + (size_t)(m0 + arow) * D + acol;
    const float* Bg = B + (size_t)brow * D + n0 + bcol;

    float4 a0 = *(const float4*)(Ag);
    float4 a1 = *(const float4*)(Ag + (size_t)64 * D);
    float4 b0 = *(const float4*)(Bg);
    float4 b1 = *(const float4*)(Bg + (size_t)8 * D);

    float acc[8][8];
#pragma unroll
    for (int i = 0; i < 8; i++)
#pragma unroll
        for (int j = 0; j < 8; j++) acc[i][j] = 0.0f;

#pragma unroll 1
    for (int kt = 0; kt < D / BK; ++kt) {
        // commit prefetched tile to smem (A stored transposed: As[k][m])
        As[acol + 0][arow]      = a0.x;
        As[acol + 1][arow]      = a0.y;
        As[acol + 2][arow]      = a0.z;
        As[acol + 3][arow]      = a0.w;
        As[acol + 0][arow + 64] = a1.x;
        As[acol + 1][arow + 64] = a1.y;
        As[acol + 2][arow + 64] = a1.z;
        As[acol + 3][arow + 64] = a1.w;
        *(float4*)&Bs[brow][bcol]     = b0;
        *(float4*)&Bs[brow + 8][bcol] = b1;
        __syncthreads();

        if (kt < D / BK - 1) {   // prefetch next tile into regs
            const float* Agn = Ag + (kt + 1) * BK;
            const float* Bgn = Bg + (size_t)(kt + 1) * BK * D;
            a0 = *(const float4*)(Agn);
            a1 = *(const float4*)(Agn + (size_t)64 * D);
            b0 = *(const float4*)(Bgn);
            b1 = *(const float4*)(Bgn + (size_t)8 * D);
        }

#pragma unroll
        for (int kk = 0; kk < BK; ++kk) {
            float ar[8], br[8];
            *(float4*)&ar[0] = *(const float4*)&As[kk][ty * 8];
            *(float4*)&ar[4] = *(const float4*)&As[kk][ty * 8 + 4];
            *(float4*)&br[0] = *(const float4*)&Bs[kk][tx * 8];
            *(float4*)&br[4] = *(const float4*)&Bs[kk][tx * 8 + 4];
#pragma unroll
            for (int i = 0; i < 8; i++)
#pragma unroll
                for (int j = 0; j < 8; j++)
                    acc[i][j] = fmaf(ar[i], br[j], acc[i][j]);
        }
        __syncthreads();
    }

    // ---- epilogue ----
    const int mrow = m0 + ty * 8;
    const int ncol = n0 + tx * 8;

    if (MODE == 0) {
        float bv[8];
#pragma unroll
        for (int j = 0; j < 8; j++) bv[j] = bias[ncol + j];
#pragma unroll
        for (int i = 0; i < 8; i++) {
            size_t off = (size_t)(mrow + i) * D + ncol;
#pragma unroll
            for (int j = 0; j < 8; j++)
                g_H1[off + j] = tanhf(acc[i][j] + bv[j]);
        }
    } else if (MODE == 1) {
        float bv[8], wv[8];
#pragma unroll
        for (int j = 0; j < 8; j++) { bv[j] = bias[ncol + j]; wv[j] = wout[ncol + j]; }
#pragma unroll
        for (int i = 0; i < 8; i++) {
            size_t off = (size_t)(mrow + i) * D + ncol;
#pragma unroll
            for (int j = 0; j < 8; j++) {
                float t = tanhf(acc[i][j] + bv[j]);
                g_G2[off + j] = wv[j] * (1.0f - t * t);
            }
        }
    } else if (MODE == 2) {
        #pragma unroll
        for (int i = 0; i < 8; i++) {
            size_t off = (size_t)(mrow + i) * D + ncol;
#pragma unroll
            for (int j = 0; j < 8; j++) {
                float h = g_H1[off + j];
                g_G1[off + j] = acc[i][j] * (1.0f - h * h);
            }
        }
    } else if (MODE == 3) {
#pragma unroll
        for (int i = 0; i < 8; i++) {
            int m = mrow + i;
            float dt = (m < BHALF) ? DT_MAG : -DT_MAG;
            size_t soff = (size_t)m * D;
#pragma unroll
            for (int j = 0; j < 8; j++) {
                int n = ncol + j;
                if (n < FD) {
                    // dp = -dH[:, :FD]; p += 0.5*dt*dp
                    g_S[soff + FD + n] -= 0.5f * dt * acc[i][j];
                } else {
                    // dq = dH[:, FD:]; q += dt*dq
                    g_S[soff + (n - FD)] += dt * acc[i][j];
                }
            }
        }
    } else {  // MODE 4: final half-kick only, launched with gridDim.y == 1
#pragma unroll
        for (int i = 0; i < 8; i++) {
            int m = mrow + i;
            float dt = (m < BHALF) ? DT_MAG : -DT_MAG;
            size_t soff = (size_t)m * D;
#pragma unroll
            for (int j = 0; j < 8; j++)
                g_S[soff + FD + ncol + j] -= 0.5f * dt * acc[i][j];
        }
    }
}

// ----------------------------------------------------------------------------
extern "C" void kernel_launch(void* const* d_in, const int* in_sizes, int n_in,
                              void* d_out, int out_size) {
    const float* x    = (const float*)d_in[0];
    const float* W1   = (const float*)d_in[1];
    const float* b1   = (const float*)d_in[2];
    const float* W2   = (const float*)d_in[3];
    const float* b2   = (const float*)d_in[4];
    const float* Wout = (const float*)d_in[5];
    float* out = (float*)d_out;

    prep_kernel<<<D * D / 256, 256>>>(W1, W2);
    init_kernel<<<BHALF, 128>>>(x);

    dim3 blk(NTHREADS);
    dim3 gFull(MTOT / BM, D / BN);   // (128, 2)
    dim3 gHalf(MTOT / BM, 1);        // (128, 1)

    for (int step = 0; step < 4; ++step) {
        // eval 1: gradients at (q,p); p += 0.5*dt*dp; q += dt*dq
        gemm_kernel<0><<<gFull, blk>>>(W1, b1, nullptr);
        gemm_kernel<1><<<gFull, blk>>>(W2, b2, Wout);
        gemm_kernel<2><<<gFull, blk>>>(nullptr, nullptr, nullptr);
        gemm_kernel<3><<<gFull, blk>>>(nullptr, nullptr, nullptr);
        // eval 2: gradients at updated (q,p); p += 0.5*dt*dp (dq discarded ->
        // only first 128 output columns of pass 4 are needed)
        gemm_kernel<0><<<gFull, blk>>>(W1, b1, nullptr);
        gemm_kernel<1><<<gFull, blk>>>(W2, b2, Wout);
        gemm_kernel<2><<<gFull, blk>>>(nullptr, nullptr, nullptr);
        gemm_kernel<4><<<gHalf, blk>>>(nullptr, nullptr, nullptr);
    }

    final_kernel<<<BHALF, 128>>>(x, out);
}

// round 3
// speedup vs baseline: 2.6843x; 2.6843x over previous
#include <cuda_runtime.h>
#include <math.h>
#include <cstdint>

// ============================================================================
// BiDirectionalSymplecticLayer — tensor-core version via generic-PTX
// mma.sync.m16n8k8 tf32 (compute_103-safe; tcgen05 PTX is rejected by this
// harness's compute_103 lowering).
//
// 8 sequential gradient evals over M=16384 rows (rows 0..8191 fwd dt=+0.1,
// rows 8192..16383 bwd dt=-0.1). Each eval = 4 GEMMs (M,256)x(256,256) with
// fused elementwise epilogues; pass 4 of the 2nd eval per step is half-size.
// ============================================================================

#define D       256
#define FD      128
#define MTOT    16384
#define BHALF   8192
#define DT_MAG  0.1f

#define BM 128
#define BN 128
#define BK 32
#define NTH 256

// smem strides (words) chosen for conflict-free fragment LDS
#define ASTR 36     // As[m][k], bank = (36m + k)%32 = (4m+k)%32
#define BSTR 136    // Bs[k][n], bank = (136k + n)%32 = (8k+n)%32
#define ABYTES (BM * ASTR * 4)      // 18432
#define BBYTES (BK * BSTR * 4)      // 17408
#define SMEM_TOTAL (2 * ABYTES + 2 * BBYTES)   // 71680

__device__ float g_S  [MTOT * D];
__device__ float g_H1 [MTOT * D];
__device__ float g_G2 [MTOT * D];
__device__ float g_G1 [MTOT * D];
__device__ float g_W1r[D * D];   // tf32-rounded W1
__device__ float g_W2r[D * D];   // tf32-rounded W2
__device__ float g_W1T[D * D];   // tf32-rounded W1^T
__device__ float g_W2T[D * D];   // tf32-rounded W2^T

// ------------------------------- helpers ------------------------------------
__device__ __forceinline__ float tf32r(float x) {
    uint32_t u;
    asm("cvt.rna.tf32.f32 %0, %1;" : "=r"(u) : "f"(x));
    return __uint_as_float(u);
}
__device__ __forceinline__ void cpa16(uint32_t dst, const float* src) {
    asm volatile("cp.async.cg.shared.global [%0], [%1], 16;"
                 :: "r"(dst), "l"(src) : "memory");
}
__device__ __forceinline__ uint32_t smem_u32(const void* p) {
    uint32_t r;
    asm("{ .reg .u64 t; cvta.to.shared.u64 t, %1; cvt.u32.u64 %0, t; }"
        : "=r"(r) : "l"(p));
    return r;
}
__device__ __forceinline__ void mma8(float* c, const uint32_t* a, const uint32_t* b) {
    asm volatile(
        "mma.sync.aligned.m16n8k8.row.col.f32.tf32.tf32.f32 "
        "{%0,%1,%2,%3}, {%4,%5,%6,%7}, {%8,%9}, {%0,%1,%2,%3};"
        : "+f"(c[0]), "+f"(c[1]), "+f"(c[2]), "+f"(c[3])
        : "r"(a[0]), "r"(a[1]), "r"(a[2]), "r"(a[3]), "r"(b[0]), "r"(b[1]));
}

// --------------------------- prologue kernels -------------------------------
__global__ void prep_kernel(const float* __restrict__ W1,
                            const float* __restrict__ W2) {
    int idx = blockIdx.x * blockDim.x + threadIdx.x;   // 65536
    int r = idx >> 8, c = idx & 255;
    float v1 = tf32r(W1[idx]);
    float v2 = tf32r(W2[idx]);
    g_W1r[idx] = v1;  g_W1T[c * D + r] = v1;
    g_W2r[idx] = v2;  g_W2T[c * D + r] = v2;
}

__global__ void init_kernel(const float* __restrict__ x) {
    int b = blockIdx.x, f = threadIdx.x;
    size_t xb = (size_t)b * 64 * 128;
    float xm  = x[xb + 32 * 128 + f];
    float xm1 = x[xb + 31 * 128 + f];
    float q = xm, p = xm - xm1;
    g_S[(size_t)b * D + f]                = q;
    g_S[(size_t)b * D + FD + f]           = p;
    g_S[(size_t)(BHALF + b) * D + f]      = q;
    g_S[(size_t)(BHALF + b) * D + FD + f] = p;
}

__global__ void final_kernel(const float* __restrict__ x,
                             float* __restrict__ out) {
    int b = blockIdx.x, f = threadIdx.x;
    size_t xb = (size_t)b * 64 * 128;
    float xm  = x[xb + 32 * 128 + f];
    float xm1 = x[xb + 31 * 128 + f];
    size_t ob = (size_t)b * 768;
    size_t sf = (size_t)b * D;
    size_t sb = (size_t)(BHALF + b) * D;
    out[ob + 0 * FD + f] = g_S[sb + f];
    out[ob + 1 * FD + f] = g_S[sb + FD + f];
    out[ob + 2 * FD + f] = xm;
    out[ob + 3 * FD + f] = xm - xm1;
    out[ob + 4 * FD + f] = g_S[sf + f];
    out[ob + 5 * FD + f] = g_S[sf + FD + f];
}

// ------------------------------ GEMM kernel ---------------------------------
//  MODE 0: A=g_S  (cvt->tf32), B=g_W1r -> g_H1 = tf32(tanh(acc + b1[n]))
//  MODE 1: A=g_H1,             B=g_W2r -> g_G2 = tf32(wout[n]*(1-tanh(acc+b2[n])^2))
//  MODE 2: A=g_G2,             B=g_W2T -> g_G1 = tf32(acc * (1 - g_H1^2))
//  MODE 3: A=g_G1,             B=g_W1T -> y=0: p -= 0.5*dt*acc ; y=1: q += dt*acc
//  MODE 4: A=g_G1,             B=g_W1T -> (grid.y=1) p -= 0.5*dt*acc
template <int MODE>
__global__ void __launch_bounds__(NTH, 2)
mma_pass(const float* __restrict__ bias, const float* __restrict__ wout) {
    extern __shared__ __align__(16) char smem[];
    const uint32_t sb = smem_u32(smem);
    const uint32_t aoff[2] = {0u, (uint32_t)ABYTES};
    const uint32_t boff[2] = {2u * ABYTES, 2u * ABYTES + BBYTES};

    const int tid  = threadIdx.x;
    const int wid  = tid >> 5;
    const int lane = tid & 31;
    const int g    = lane >> 2;    // groupID 0..7
    const int t    = lane & 3;     // thread-in-group 0..3
    const int wm   = (wid & 1) * 64;
    const int wn   = (wid >> 1) * 32;
    const int m0   = blockIdx.x * BM;
    const int n0   = blockIdx.y * BN;

    const float* A;
    const float* B;
    if (MODE == 0)      { A = g_S;  B = g_W1r; }
    else if (MODE == 1) { A = g_H1; B = g_W2r; }
    else if (MODE == 2) { A = g_G2; B = g_W2T; }
    else                { A = g_G1; B = g_W1T; }

    float acc[4][4][4];
#pragma unroll
    for (int f = 0; f < 4; f++)
#pragma unroll
        for (int nf = 0; nf < 4; nf++)
#pragma unroll
            for (int r = 0; r < 4; r++) acc[f][nf][r] = 0.0f;

    // ---- chunk loader: A 128x32 row-major(stride ASTR), B 32x128 (stride BSTR)
    auto load_chunk = [&](int kc, int b) {
        const float* Ag = A + (size_t)m0 * D + kc * BK;
#pragma unroll
        for (int i = 0; i < 4; i++) {            // 1024 xfers / 256 threads
            int idx = tid + (i << 8);
            int row = idx >> 3, c = idx & 7;     // row 0..127, c 0..7 (x4 floats)
            cpa16(sb + aoff[b] + (uint32_t)(row * ASTR + c * 4) * 4,
                  Ag + (size_t)row * D + c * 4);
        }
        const float* Bg = B + (size_t)kc * BK * D + n0;
#pragma unroll
        for (int i = 0; i < 4; i++) {
            int idx = tid + (i << 8);
            int row = idx >> 5, c = idx & 31;    // row 0..31, c 0..31 (x4 floats)
            cpa16(sb + boff[b] + (uint32_t)(row * BSTR + c * 4) * 4,
                  Bg + (size_t)row * D + c * 4);
        }
        asm volatile("cp.async.commit_group;" ::: "memory");
    };

    load_chunk(0, 0);
    load_chunk(1, 1);

#pragma unroll 1
    for (int kc = 0; kc < D / BK; kc++) {
        const int b = kc & 1;
        if (kc < D / BK - 1) asm volatile("cp.async.wait_group 1;" ::: "memory");
        else                 asm volatile("cp.async.wait_group 0;" ::: "memory");
        __syncthreads();

        const float* As = (const float*)(smem + aoff[b]);
        const float* Bs = (const float*)(smem + boff[b]);

#pragma unroll
        for (int kk = 0; kk < BK / 8; kk++) {
            const int k0 = kk * 8;
            uint32_t a[4][4], bb[4][2];
#pragma unroll
            for (int f = 0; f < 4; f++) {
                const float* ap = As + (wm + f * 16 + g) * ASTR + k0 + t;
                a[f][0] = __float_as_uint(ap[0]);
                a[f][1] = __float_as_uint(ap[8 * ASTR]);
                a[f][2] = __float_as_uint(ap[4]);
                a[f][3] = __float_as_uint(ap[8 * ASTR + 4]);
                if (MODE == 0) {
#pragma unroll
                    for (int r = 0; r < 4; r++)
                        a[f][r] = __float_as_uint(tf32r(__uint_as_float(a[f][r])));
                }
            }
#pragma unroll
            for (int nf = 0; nf < 4; nf++) {
                const float* bp = Bs + (k0 + t) * BSTR + wn + nf * 8 + g;
                bb[nf][0] = __float_as_uint(bp[0]);
                bb[nf][1] = __float_as_uint(bp[4 * BSTR]);
            }
#pragma unroll
            for (int f = 0; f < 4; f++)
#pragma unroll
                for (int nf = 0; nf < 4; nf++)
                    mma8(acc[f][nf], a[f], bb[nf]);
        }
        __syncthreads();
        if (kc + 2 < D / BK) load_chunk(kc + 2, b);
    }

    // ------------------------------ epilogue --------------------------------
    const float dt = (m0 < BHALF) ? DT_MAG : -DT_MAG;   // uniform per CTA

#pragma unroll
    for (int f = 0; f < 4; f++) {
        const int mr = m0 + wm + f * 16 + g;            // rows mr, mr+8
#pragma unroll
        for (int nf = 0; nf < 4; nf++) {
            const int nc = n0 + wn + nf * 8 + 2 * t;    // cols nc, nc+1
            float c0 = acc[f][nf][0], c1 = acc[f][nf][1];
            float c2 = acc[f][nf][2], c3 = acc[f][nf][3];

            if (MODE == 0) {
                float bv0 = bias[nc], bv1 = bias[nc + 1];
                float* d0 = g_H1 + (size_t)mr * D + nc;
                float* d1 = g_H1 + (size_t)(mr + 8) * D + nc;
                d0[0] = tf32r(tanhf(c0 + bv0));
                d0[1] = tf32r(tanhf(c1 + bv1));
                d1[0] = tf32r(tanhf(c2 + bv0));
                d1[1] = tf32r(tanhf(c3 + bv1));
            } else if (MODE == 1) {
                float bv0 = bias[nc], bv1 = bias[nc + 1];
                float wv0 = wout[nc], wv1 = wout[nc + 1];
                float* d0 = g_G2 + (size_t)mr * D + nc;
                float* d1 = g_G2 + (size_t)(mr + 8) * D + nc;
                float t0 = tanhf(c0 + bv0), t1 = tanhf(c1 + bv1);
                float t2 = tanhf(c2 + bv0), t3 = tanhf(c3 + bv1);
                d0[0] = tf32r(wv0 * (1.0f - t0 * t0));
                d0[1] = tf32r(wv1 * (1.0f - t1 * t1));
                d1[0] = tf32r(wv0 * (1.0f - t2 * t2));
                d1[1] = tf32r(wv1 * (1.0f - t3 * t3));
            } else if (MODE == 2) {
                const float* h0 = g_H1 + (size_t)mr * D + nc;
                const float* h1 = g_H1 + (size_t)(mr + 8) * D + nc;
                float* d0 = g_G1 + (size_t)mr * D + nc;
                float* d1 = g_G1 + (size_t)(mr + 8) * D + nc;
                float a0 = h0[0], a1 = h0[1], a2 = h1[0], a3 = h1[1];
                d0[0] = tf32r(c0 * (1.0f - a0 * a0));
                d0[1] = tf32r(c1 * (1.0f - a1 * a1));
                d1[0] = tf32r(c2 * (1.0f - a2 * a2));
                d1[1] = tf32r(c3 * (1.0f - a3 * a3));
            } else if (MODE == 3) {
                float* S0 = g_S + (size_t)mr * D;
                float* S1 = g_S + (size_t)(mr + 8) * D;
                if (n0 == 0) {          // dp = -dH[:, :FD]; p += 0.5*dt*dp
                    S0[FD + nc]     -= 0.5f * dt * c0;
                    S0[FD + nc + 1] -= 0.5f * dt * c1;
                    S1[FD + nc]     -= 0.5f * dt * c2;
                    S1[FD + nc + 1] -= 0.5f * dt * c3;
                } else {                // dq = dH[:, FD:]; q += dt*dq
                    int qc = nc - FD;
                    S0[qc]     += dt * c0;
                    S0[qc + 1] += dt * c1;
                    S1[qc]     += dt * c2;
                    S1[qc + 1] += dt * c3;
                }
            } else {                    // MODE 4: final half-kick (grid.y = 1)
                float* S0 = g_S + (size_t)mr * D;
                float* S1 = g_S + (size_t)(mr + 8) * D;
                S0[FD + nc]     -= 0.5f * dt * c0;
                S0[FD + nc + 1] -= 0.5f * dt * c1;
                S1[FD + nc]     -= 0.5f * dt * c2;
                S1[FD + nc + 1] -= 0.5f * dt * c3;
            }
        }
    }
}

// ---------------------------------------------------------------------------
extern "C" void kernel_launch(void* const* d_in, const int* in_sizes, int n_in,
                              void* d_out, int out_size) {
    const float* x    = (const float*)d_in[0];
    const float* W1   = (const float*)d_in[1];
    const float* b1   = (const float*)d_in[2];
    const float* W2   = (const float*)d_in[3];
    const float* b2   = (const float*)d_in[4];
    const float* Wout = (const float*)d_in[5];
    float* out = (float*)d_out;

    static bool attr_done = false;
    if (!attr_done) {
        cudaFuncSetAttribute(mma_pass<0>, cudaFuncAttributeMaxDynamicSharedMemorySize, SMEM_TOTAL);
        cudaFuncSetAttribute(mma_pass<1>, cudaFuncAttributeMaxDynamicSharedMemorySize, SMEM_TOTAL);
        cudaFuncSetAttribute(mma_pass<2>, cudaFuncAttributeMaxDynamicSharedMemorySize, SMEM_TOTAL);
        cudaFuncSetAttribute(mma_pass<3>, cudaFuncAttributeMaxDynamicSharedMemorySize, SMEM_TOTAL);
        cudaFuncSetAttribute(mma_pass<4>, cudaFuncAttributeMaxDynamicSharedMemorySize, SMEM_TOTAL);
        attr_done = true;
    }

    prep_kernel<<<D * D / 256, 256>>>(W1, W2);
    init_kernel<<<BHALF, 128>>>(x);

    dim3 blk(NTH);
    dim3 gFull(MTOT / BM, D / BN);   // (128, 2)
    dim3 gHalf(MTOT / BM, 1);        // (128, 1)

    for (int step = 0; step < 4; ++step) {
        mma_pass<0><<<gFull, blk, SMEM_TOTAL>>>(b1, nullptr);
        mma_pass<1><<<gFull, blk, SMEM_TOTAL>>>(b2, Wout);
        mma_pass<2><<<gFull, blk, SMEM_TOTAL>>>(nullptr, nullptr);
        mma_pass<3><<<gFull, blk, SMEM_TOTAL>>>(nullptr, nullptr);
        mma_pass<0><<<gFull, blk, SMEM_TOTAL>>>(b1, nullptr);
        mma_pass<1><<<gFull, blk, SMEM_TOTAL>>>(b2, Wout);
        mma_pass<2><<<gFull, blk, SMEM_TOTAL>>>(nullptr, nullptr);
        mma_pass<4><<<gHalf, blk, SMEM_TOTAL>>>(nullptr, nullptr);
    }

    final_kernel<<<BHALF, 128>>>(x, out);
}

// round 4
// speedup vs baseline: 3.9213x; 1.4608x over previous
#include <cuda_runtime.h>
#include <cuda_bf16.h>
#include <math.h>
#include <cstdint>

// ============================================================================
// BiDirectionalSymplecticLayer — bf16 m16n8k16 mma.sync version.
// 8 sequential gradient evals over M=16384 rows (rows 0..8191 fwd dt=+0.1,
// rows 8192..16383 bwd dt=-0.1). Each eval = 4 GEMMs (M,256)x(256,256) with
// fused epilogues; last pass of the 2nd eval per step is half-size.
// State g_S kept fp32 (exact accumulation); all GEMM operands bf16.
// ============================================================================

#define D       256
#define FD      128
#define MTOT    16384
#define BHALF   8192
#define DT_MAG  0.1f

#define BM 128
#define BN 128
#define BK 32          // K elements per chunk (32 bf16 = 64B/row)
#define NTH 256

// smem: rows of 32 bf16 (64B) padded to 80B -> 20 words stride, conflict-free
#define RSTR 20
#define TILEB (128 * RSTR * 4)          // 10240 bytes per tile buffer
#define SMEM_TOTAL (4 * TILEB)          // A0,A1,B0,B1 = 40960

__device__ float         g_S  [MTOT * D];   // fp32 state [q|p]
__device__ __nv_bfloat16 g_Sb [MTOT * D];   // bf16 shadow of state
__device__ __nv_bfloat16 g_H1 [MTOT * D];
__device__ __nv_bfloat16 g_G2 [MTOT * D];
__device__ __nv_bfloat16 g_G1 [MTOT * D];
// weights as bf16, stored n-major [n][k] for the B operand of each mode
__device__ __nv_bfloat16 g_W1b [D * D];   // = W1[n][k]   (for G1 @ W1^T)
__device__ __nv_bfloat16 g_W2b [D * D];   // = W2[n][k]   (for G2 @ W2^T)
__device__ __nv_bfloat16 g_W1Tb[D * D];   // = W1[k][n] transposed (for S @ W1)
__device__ __nv_bfloat16 g_W2Tb[D * D];   // = W2 transposed      (for H1 @ W2)

// ------------------------------- helpers ------------------------------------
__device__ __forceinline__ void cpa16(uint32_t dst, const void* src) {
    asm volatile("cp.async.cg.shared.global [%0], [%1], 16;"
                 :: "r"(dst), "l"(src) : "memory");
}
__device__ __forceinline__ uint32_t smem_u32(const void* p) {
    uint32_t r;
    asm("{ .reg .u64 t; cvta.to.shared.u64 t, %1; cvt.u32.u64 %0, t; }"
        : "=r"(r) : "l"(p));
    return r;
}
__device__ __forceinline__ void mma16(float* c, const uint32_t* a, const uint32_t* b) {
    asm volatile(
        "mma.sync.aligned.m16n8k16.row.col.f32.bf16.bf16.f32 "
        "{%0,%1,%2,%3}, {%4,%5,%6,%7}, {%8,%9}, {%0,%1,%2,%3};"
        : "+f"(c[0]), "+f"(c[1]), "+f"(c[2]), "+f"(c[3])
        : "r"(a[0]), "r"(a[1]), "r"(a[2]), "r"(a[3]), "r"(b[0]), "r"(b[1]));
}
__device__ __forceinline__ __nv_bfloat162 pack2(float x, float y) {
    return __floats2bfloat162_rn(x, y);
}

// --------------------------- prologue kernels -------------------------------
__global__ void prep_kernel(const float* __restrict__ W1,
                            const float* __restrict__ W2) {
    int idx = blockIdx.x * blockDim.x + threadIdx.x;   // 65536
    int r = idx >> 8, c = idx & 255;                   // W[r][c], r=k, c=n
    __nv_bfloat16 v1 = __float2bfloat16(W1[idx]);
    __nv_bfloat16 v2 = __float2bfloat16(W2[idx]);
    g_W1b[idx] = v1;            // [n][k] view of W1^T-as-B == W1 row-major
    g_W2b[idx] = v2;
    g_W1Tb[c * D + r] = v1;     // [n][k] view of W1-as-B == transpose
    g_W2Tb[c * D + r] = v2;
}

__global__ void init_kernel(const float* __restrict__ x) {
    int b = blockIdx.x, f = threadIdx.x;
    size_t xb = (size_t)b * 64 * 128;
    float xm  = x[xb + 32 * 128 + f];
    float xm1 = x[xb + 31 * 128 + f];
    float q = xm, p = xm - xm1;
    size_t o0 = (size_t)b * D, o1 = (size_t)(BHALF + b) * D;
    g_S[o0 + f] = q;       g_S[o0 + FD + f] = p;
    g_S[o1 + f] = q;       g_S[o1 + FD + f] = p;
    __nv_bfloat16 qb = __float2bfloat16(q), pb = __float2bfloat16(p);
    g_Sb[o0 + f] = qb;     g_Sb[o0 + FD + f] = pb;
    g_Sb[o1 + f] = qb;     g_Sb[o1 + FD + f] = pb;
}

__global__ void final_kernel(const float* __restrict__ x,
                             float* __restrict__ out) {
    int b = blockIdx.x, f = threadIdx.x;
    size_t xb = (size_t)b * 64 * 128;
    float xm  = x[xb + 32 * 128 + f];
    float xm1 = x[xb + 31 * 128 + f];
    size_t ob = (size_t)b * 768;
    size_t sf = (size_t)b * D;
    size_t sb = (size_t)(BHALF + b) * D;
    out[ob + 0 * FD + f] = g_S[sb + f];
    out[ob + 1 * FD + f] = g_S[sb + FD + f];
    out[ob + 2 * FD + f] = xm;
    out[ob + 3 * FD + f] = xm - xm1;
    out[ob + 4 * FD + f] = g_S[sf + f];
    out[ob + 5 * FD + f] = g_S[sf + FD + f];
}

// ------------------------------ GEMM kernel ---------------------------------
//  MODE 0: A=g_Sb, B=g_W1Tb -> g_H1 = bf16(tanh(acc + b1[n]))
//  MODE 1: A=g_H1, B=g_W2Tb -> g_G2 = bf16(wout[n]*(1-tanh(acc+b2[n])^2))
//  MODE 2: A=g_G2, B=g_W2b  -> g_G1 = bf16(acc * (1 - g_H1^2))
//  MODE 3: A=g_G1, B=g_W1b  -> y=0: p -= 0.5*dt*acc ; y=1: q += dt*acc (S+Sb)
//  MODE 4: A=g_G1, B=g_W1b  -> (grid.y=1) p -= 0.5*dt*acc (S+Sb)
template <int MODE>
__global__ void __launch_bounds__(NTH, 2)
mma_pass(const float* __restrict__ bias, const float* __restrict__ wout) {
    extern __shared__ __align__(16) char smem[];
    const uint32_t sbase = smem_u32(smem);
    const uint32_t aoff[2] = {0u, (uint32_t)TILEB};
    const uint32_t boff[2] = {2u * TILEB, 3u * TILEB};

    const int tid  = threadIdx.x;
    const int wid  = tid >> 5;
    const int lane = tid & 31;
    const int g    = lane >> 2;    // 0..7
    const int t    = lane & 3;     // 0..3
    const int wm   = (wid & 1) * 64;
    const int wn   = (wid >> 1) * 32;
    const int m0   = blockIdx.x * BM;
    const int n0   = blockIdx.y * BN;

    const __nv_bfloat16* A;
    const __nv_bfloat16* B;
    if (MODE == 0)      { A = g_Sb; B = g_W1Tb; }
    else if (MODE == 1) { A = g_H1; B = g_W2Tb; }
    else if (MODE == 2) { A = g_G2; B = g_W2b; }
    else                { A = g_G1; B = g_W1b; }

    float acc[4][4][4];
#pragma unroll
    for (int f = 0; f < 4; f++)
#pragma unroll
        for (int nf = 0; nf < 4; nf++)
#pragma unroll
            for (int r = 0; r < 4; r++) acc[f][nf][r] = 0.0f;

    // ---- chunk loader: A 128x32 [m][k], B 128x32 [n][k]; rows 64B+16B pad
    auto load_chunk = [&](int kc, int b) {
        const __nv_bfloat16* Ag = A + (size_t)m0 * D + kc * BK;
#pragma unroll
        for (int i = 0; i < 2; i++) {            // 512 xfers / 256 threads
            int idx = tid + (i << 8);
            int row = idx >> 2, c = idx & 3;     // row 0..127, c 0..3 (16B each)
            cpa16(sbase + aoff[b] + (uint32_t)(row * 80 + c * 16),
                  Ag + (size_t)row * D + c * 8);
        }
        const __nv_bfloat16* Bg = B + (size_t)n0 * D + kc * BK;
#pragma unroll
        for (int i = 0; i < 2; i++) {
            int idx = tid + (i << 8);
            int row = idx >> 2, c = idx & 3;
            cpa16(sbase + boff[b] + (uint32_t)(row * 80 + c * 16),
                  Bg + (size_t)row * D + c * 8);
        }
        asm volatile("cp.async.commit_group;" ::: "memory");
    };

    load_chunk(0, 0);
    load_chunk(1, 1);

#pragma unroll 1
    for (int kc = 0; kc < D / BK; kc++) {
        const int b = kc & 1;
        if (kc < D / BK - 1) asm volatile("cp.async.wait_group 1;" ::: "memory");
        else                 asm volatile("cp.async.wait_group 0;" ::: "memory");
        __syncthreads();

        const uint32_t* As = (const uint32_t*)(smem + aoff[b]);
        const uint32_t* Bs = (const uint32_t*)(smem + boff[b]);

#pragma unroll
        for (int kk = 0; kk < 2; kk++) {          // two k16 steps per 32-chunk
            const int kw = kk * 8;                // word offset in row
            uint32_t a[4][4], bb[4][2];
#pragma unroll
            for (int f = 0; f < 4; f++) {
                const int r0 = wm + f * 16 + g;
                a[f][0] = As[r0 * RSTR + kw + t];
                a[f][1] = As[(r0 + 8) * RSTR + kw + t];
                a[f][2] = As[r0 * RSTR + kw + 4 + t];
                a[f][3] = As[(r0 + 8) * RSTR + kw + 4 + t];
            }
#pragma unroll
            for (int nf = 0; nf < 4; nf++) {
                const int nr = wn + nf * 8 + g;
                bb[nf][0] = Bs[nr * RSTR + kw + t];
                bb[nf][1] = Bs[nr * RSTR + kw + 4 + t];
            }
#pragma unroll
            for (int f = 0; f < 4; f++)
#pragma unroll
                for (int nf = 0; nf < 4; nf++)
                    mma16(acc[f][nf], a[f], bb[nf]);
        }
        __syncthreads();
        if (kc + 2 < D / BK) load_chunk(kc + 2, b);
    }

    // ------------------------------ epilogue --------------------------------
    const float dt = (m0 < BHALF) ? DT_MAG : -DT_MAG;   // uniform per CTA

#pragma unroll
    for (int f = 0; f < 4; f++) {
        const int mr = m0 + wm + f * 16 + g;            // rows mr, mr+8
#pragma unroll
        for (int nf = 0; nf < 4; nf++) {
            const int nc = n0 + wn + nf * 8 + 2 * t;    // cols nc, nc+1 (even)
            float c0 = acc[f][nf][0], c1 = acc[f][nf][1];
            float c2 = acc[f][nf][2], c3 = acc[f][nf][3];

            if (MODE == 0) {
                float bv0 = bias[nc], bv1 = bias[nc + 1];
                *(__nv_bfloat162*)(g_H1 + (size_t)mr * D + nc) =
                    pack2(tanhf(c0 + bv0), tanhf(c1 + bv1));
                *(__nv_bfloat162*)(g_H1 + (size_t)(mr + 8) * D + nc) =
                    pack2(tanhf(c2 + bv0), tanhf(c3 + bv1));
            } else if (MODE == 1) {
                float bv0 = bias[nc], bv1 = bias[nc + 1];
                float wv0 = wout[nc], wv1 = wout[nc + 1];
                float t0 = tanhf(c0 + bv0), t1 = tanhf(c1 + bv1);
                float t2 = tanhf(c2 + bv0), t3 = tanhf(c3 + bv1);
                *(__nv_bfloat162*)(g_G2 + (size_t)mr * D + nc) =
                    pack2(wv0 * (1.0f - t0 * t0), wv1 * (1.0f - t1 * t1));
                *(__nv_bfloat162*)(g_G2 + (size_t)(mr + 8) * D + nc) =
                    pack2(wv0 * (1.0f - t2 * t2), wv1 * (1.0f - t3 * t3));
            } else if (MODE == 2) {
                __nv_bfloat162 h0 = *(const __nv_bfloat162*)(g_H1 + (size_t)mr * D + nc);
                __nv_bfloat162 h1 = *(const __nv_bfloat162*)(g_H1 + (size_t)(mr + 8) * D + nc);
                float a0 = __bfloat162float(h0.x), a1 = __bfloat162float(h0.y);
                float a2 = __bfloat162float(h1.x), a3 = __bfloat162float(h1.y);
                *(__nv_bfloat162*)(g_G1 + (size_t)mr * D + nc) =
                    pack2(c0 * (1.0f - a0 * a0), c1 * (1.0f - a1 * a1));
                *(__nv_bfloat162*)(g_G1 + (size_t)(mr + 8) * D + nc) =
                    pack2(c2 * (1.0f - a2 * a2), c3 * (1.0f - a3 * a3));
            } else if (MODE == 3) {
                float* S0 = g_S + (size_t)mr * D;
                float* S1 = g_S + (size_t)(mr + 8) * D;
                __nv_bfloat16* Sb0 = g_Sb + (size_t)mr * D;
                __nv_bfloat16* Sb1 = g_Sb + (size_t)(mr + 8) * D;
                if (n0 == 0) {          // dp = -dH[:, :FD]; p += 0.5*dt*dp
                    float p00 = S0[FD + nc]     - 0.5f * dt * c0;
                    float p01 = S0[FD + nc + 1] - 0.5f * dt * c1;
                    float p10 = S1[FD + nc]     - 0.5f * dt * c2;
                    float p11 = S1[FD + nc + 1] - 0.5f * dt * c3;
                    S0[FD + nc] = p00;  S0[FD + nc + 1] = p01;
                    S1[FD + nc] = p10;  S1[FD + nc + 1] = p11;
                    *(__nv_bfloat162*)(Sb0 + FD + nc) = pack2(p00, p01);
                    *(__nv_bfloat162*)(Sb1 + FD + nc) = pack2(p10, p11);
                } else {                // dq = dH[:, FD:]; q += dt*dq
                    int qc = nc - FD;
                    float q00 = S0[qc]     + dt * c0;
                    float q01 = S0[qc + 1] + dt * c1;
                    float q10 = S1[qc]     + dt * c2;
                    float q11 = S1[qc + 1] + dt * c3;
                    S0[qc] = q00;  S0[qc + 1] = q01;
                    S1[qc] = q10;  S1[qc + 1] = q11;
                    *(__nv_bfloat162*)(Sb0 + qc) = pack2(q00, q01);
                    *(__nv_bfloat162*)(Sb1 + qc) = pack2(q10, q11);
                }
            } else {                    // MODE 4: final half-kick (grid.y = 1)
                float* S0 = g_S + (size_t)mr * D;
                float* S1 = g_S + (size_t)(mr + 8) * D;
                __nv_bfloat16* Sb0 = g_Sb + (size_t)mr * D;
                __nv_bfloat16* Sb1 = g_Sb + (size_t)(mr + 8) * D;
                float p00 = S0[FD + nc]     - 0.5f * dt * c0;
                float p01 = S0[FD + nc + 1] - 0.5f * dt * c1;
                float p10 = S1[FD + nc]     - 0.5f * dt * c2;
                float p11 = S1[FD + nc + 1] - 0.5f * dt * c3;
                S0[FD + nc] = p00;  S0[FD + nc + 1] = p01;
                S1[FD + nc] = p10;  S1[FD + nc + 1] = p11;
                *(__nv_bfloat162*)(Sb0 + FD + nc) = pack2(p00, p01);
                *(__nv_bfloat162*)(Sb1 + FD + nc) = pack2(p10, p11);
            }
        }
    }
}

// ---------------------------------------------------------------------------
extern "C" void kernel_launch(void* const* d_in, const int* in_sizes, int n_in,
                              void* d_out, int out_size) {
    const float* x    = (const float*)d_in[0];
    const float* W1   = (const float*)d_in[1];
    const float* b1   = (const float*)d_in[2];
    const float* W2   = (const float*)d_in[3];
    const float* b2   = (const float*)d_in[4];
    const float* Wout = (const float*)d_in[5];
    float* out = (float*)d_out;

    static bool attr_done = false;
    if (!attr_done) {
        cudaFuncSetAttribute(mma_pass<0>, cudaFuncAttributeMaxDynamicSharedMemorySize, SMEM_TOTAL);
        cudaFuncSetAttribute(mma_pass<1>, cudaFuncAttributeMaxDynamicSharedMemorySize, SMEM_TOTAL);
        cudaFuncSetAttribute(mma_pass<2>, cudaFuncAttributeMaxDynamicSharedMemorySize, SMEM_TOTAL);
        cudaFuncSetAttribute(mma_pass<3>, cudaFuncAttributeMaxDynamicSharedMemorySize, SMEM_TOTAL);
        cudaFuncSetAttribute(mma_pass<4>, cudaFuncAttributeMaxDynamicSharedMemorySize, SMEM_TOTAL);
        attr_done = true;
    }

    prep_kernel<<<D * D / 256, 256>>>(W1, W2);
    init_kernel<<<BHALF, 128>>>(x);

    dim3 blk(NTH);
    dim3 gFull(MTOT / BM, D / BN);   // (128, 2)
    dim3 gHalf(MTOT / BM, 1);        // (128, 1)

    for (int step = 0; step < 4; ++step) {
        mma_pass<0><<<gFull, blk, SMEM_TOTAL>>>(b1, nullptr);
        mma_pass<1><<<gFull, blk, SMEM_TOTAL>>>(b2, Wout);
        mma_pass<2><<<gFull, blk, SMEM_TOTAL>>>(nullptr, nullptr);
        mma_pass<3><<<gFull, blk, SMEM_TOTAL>>>(nullptr, nullptr);
        mma_pass<0><<<gFull, blk, SMEM_TOTAL>>>(b1, nullptr);
        mma_pass<1><<<gFull, blk, SMEM_TOTAL>>>(b2, Wout);
        mma_pass<2><<<gFull, blk, SMEM_TOTAL>>>(nullptr, nullptr);
        mma_pass<4><<<gHalf, blk, SMEM_TOTAL>>>(nullptr, nullptr);
    }

    final_kernel<<<BHALF, 128>>>(x, out);
}

// round 5
// speedup vs baseline: 4.9044x; 1.2507x over previous
#include <cuda_runtime.h>
#include <cuda_bf16.h>
#include <math.h>
#include <cstdint>

// ============================================================================
// BiDirectionalSymplecticLayer — fully fused persistent kernel.
// Rows are independent through the whole algorithm, so each CTA owns 128 rows
// and runs all 8 gradient evals locally: intermediates (H1, G2/G1) live in
// shared memory; weights stream from L2; fp32 state in global (per-thread RMW).
// GEMMs: mma.sync m16n8k16 bf16, warp tile 64x64, 8 warps/CTA, 1 CTA/SM.
// ============================================================================

#define D       256
#define FD      128
#define MTOT    16384
#define BHALF   8192
#define DT_MAG  0.1f
#define BM      128

// smem layout (byte offsets). Tiles: 128 rows x 128 words (bf16x2), XOR-swizzled.
#define OFF_H   0
#define OFF_G   65536
#define OFF_B0  131072       // B staging buf 0: 256 rows x 80B
#define OFF_B1  151552
#define OFF_A0  172032       // A staging buf 0 (pass 1): 128 rows x 80B
#define OFF_A1  182272
#define OFF_B1S 192512       // bias1 (256 f32)
#define OFF_B2S 193536       // bias2
#define OFF_WO  194560       // wout
#define SMEM_TOTAL 195584

__device__ float         g_S [MTOT * D];   // fp32 state [q|p]
__device__ __nv_bfloat16 g_Sb[MTOT * D];   // bf16 shadow of state
__device__ __nv_bfloat16 g_W1b [D * D];    // W1  [n][k]  (B for pass 4)
__device__ __nv_bfloat16 g_W2b [D * D];    // W2  [n][k]  (B for pass 3)
__device__ __nv_bfloat16 g_W1Tb[D * D];    // W1^T [n][k] (B for pass 1)
__device__ __nv_bfloat16 g_W2Tb[D * D];    // W2^T [n][k] (B for pass 2)

// ------------------------------- helpers ------------------------------------
__device__ __forceinline__ void cpa16(uint32_t dst, const void* src) {
    asm volatile("cp.async.cg.shared.global [%0], [%1], 16;"
                 :: "r"(dst), "l"(src) : "memory");
}
__device__ __forceinline__ uint32_t smem_u32(const void* p) {
    uint32_t r;
    asm("{ .reg .u64 t; cvta.to.shared.u64 t, %1; cvt.u32.u64 %0, t; }"
        : "=r"(r) : "l"(p));
    return r;
}
__device__ __forceinline__ void mma16(float* c, const uint32_t* a, const uint32_t* b) {
    asm volatile(
        "mma.sync.aligned.m16n8k16.row.col.f32.bf16.bf16.f32 "
        "{%0,%1,%2,%3}, {%4,%5,%6,%7}, {%8,%9}, {%0,%1,%2,%3};"
        : "+f"(c[0]), "+f"(c[1]), "+f"(c[2]), "+f"(c[3])
        : "r"(a[0]), "r"(a[1]), "r"(a[2]), "r"(a[3]), "r"(b[0]), "r"(b[1]));
}
__device__ __forceinline__ uint32_t pk2(float x, float y) {
    __nv_bfloat162 h = __floats2bfloat162_rn(x, y);
    return *reinterpret_cast<uint32_t*>(&h);
}
__device__ __forceinline__ float2 up2(uint32_t u) {
    __nv_bfloat162 h = *reinterpret_cast<__nv_bfloat162*>(&u);
    return make_float2(__bfloat162float(h.x), __bfloat162float(h.y));
}
// fast tanh: 1 - 2/(1+e^{2x}); error few ulp, far below bf16 quantization
__device__ __forceinline__ float ftanh(float x) {
    float e;
    asm("ex2.approx.f32 %0, %1;" : "=f"(e) : "f"(x * 2.885390082f));
    float r;
    asm("rcp.approx.f32 %0, %1;" : "=f"(r) : "f"(e + 1.0f));
    return 1.0f - 2.0f * r;
}

// --------------------------- prologue kernels -------------------------------
__global__ void prep_kernel(const float* __restrict__ W1,
                            const float* __restrict__ W2) {
    int idx = blockIdx.x * blockDim.x + threadIdx.x;   // 65536
    int r = idx >> 8, c = idx & 255;                   // W[r][c]
    __nv_bfloat16 v1 = __float2bfloat16(W1[idx]);
    __nv_bfloat16 v2 = __float2bfloat16(W2[idx]);
    g_W1b[idx] = v1;
    g_W2b[idx] = v2;
    g_W1Tb[c * D + r] = v1;
    g_W2Tb[c * D + r] = v2;
}

__global__ void init_kernel(const float* __restrict__ x) {
    int b = blockIdx.x, f = threadIdx.x;
    size_t xb = (size_t)b * 64 * 128;
    float xm  = x[xb + 32 * 128 + f];
    float xm1 = x[xb + 31 * 128 + f];
    float q = xm, p = xm - xm1;
    size_t o0 = (size_t)b * D, o1 = (size_t)(BHALF + b) * D;
    g_S[o0 + f] = q;       g_S[o0 + FD + f] = p;
    g_S[o1 + f] = q;       g_S[o1 + FD + f] = p;
    __nv_bfloat16 qb = __float2bfloat16(q), pb = __float2bfloat16(p);
    g_Sb[o0 + f] = qb;     g_Sb[o0 + FD + f] = pb;
    g_Sb[o1 + f] = qb;     g_Sb[o1 + FD + f] = pb;
}

__global__ void final_kernel(const float* __restrict__ x,
                             float* __restrict__ out) {
    int b = blockIdx.x, f = threadIdx.x;
    size_t xb = (size_t)b * 64 * 128;
    float xm  = x[xb + 32 * 128 + f];
    float xm1 = x[xb + 31 * 128 + f];
    size_t ob = (size_t)b * 768;
    size_t sf = (size_t)b * D;
    size_t sb = (size_t)(BHALF + b) * D;
    out[ob + 0 * FD + f] = g_S[sb + f];
    out[ob + 1 * FD + f] = g_S[sb + FD + f];
    out[ob + 2 * FD + f] = xm;
    out[ob + 3 * FD + f] = xm - xm1;
    out[ob + 4 * FD + f] = g_S[sf + f];
    out[ob + 5 * FD + f] = g_S[sf + FD + f];
}

// ------------------------------ fused pass ----------------------------------
//  MODE 0: A = staged g_Sb, B = g_W1Tb -> H tile = tanh(acc + b1)
//  MODE 1: A = H tile,      B = g_W2Tb -> G tile = wout*(1 - tanh(acc+b2)^2)
//  MODE 2: A = G tile,      B = g_W2b  -> G tile = acc*(1 - H^2)  (overwrite)
//  MODE 3: A = G tile,      B = g_W1b  -> full kick (NT=8): p & q
//  MODE 4: A = G tile,      B = g_W1b  -> half kick (NT=4): p only
template <int MODE, int NT>
__device__ __forceinline__ void pass_gemm(char* smem, uint32_t sbase,
                                          int m0, float dtv) {
    const int tid  = threadIdx.x;
    const int wid  = tid >> 5;
    const int lane = tid & 31;
    const int g    = lane >> 2;
    const int t    = lane & 3;
    const int wm   = (wid & 1) * 64;
    const int wn   = (wid >> 1) * (NT * 8);
    const int NTOT = NT * 32;                 // 256 or 128

    const uint32_t* Ht  = (const uint32_t*)(smem + OFF_H);
    uint32_t*       Htw = (uint32_t*)(smem + OFF_H);
    uint32_t*       Gt  = (uint32_t*)(smem + OFF_G);
    const uint32_t* Bb[2] = {(const uint32_t*)(smem + OFF_B0),
                             (const uint32_t*)(smem + OFF_B1)};
    const uint32_t* Ab[2] = {(const uint32_t*)(smem + OFF_A0),
                             (const uint32_t*)(smem + OFF_A1)};
    const float* sb1 = (const float*)(smem + OFF_B1S);
    const float* sb2 = (const float*)(smem + OFF_B2S);
    const float* swo = (const float*)(smem + OFF_WO);

    const __nv_bfloat16* Bsrc =
        (MODE == 0) ? g_W1Tb : (MODE == 1) ? g_W2Tb :
        (MODE == 2) ? g_W2b : g_W1b;

    auto stage = [&](int kc, int b) {
        const __nv_bfloat16* Bg = Bsrc + kc * 32;
        const uint32_t bdst = sbase + (b ? OFF_B1 : OFF_B0);
#pragma unroll
        for (int i = 0; i < NTOT / 64; i++) {
            int idx = tid + (i << 8);
            int row = idx >> 2, c = idx & 3;
            cpa16(bdst + row * 80 + c * 16, Bg + (size_t)row * D + c * 8);
        }
        if (MODE == 0) {
            const __nv_bfloat16* Ag = g_Sb + (size_t)m0 * D + kc * 32;
            const uint32_t adst = sbase + (b ? OFF_A1 : OFF_A0);
#pragma unroll
            for (int i = 0; i < 2; i++) {
                int idx = tid + (i << 8);
                int row = idx >> 2, c = idx & 3;
                cpa16(adst + row * 80 + c * 16, Ag + (size_t)row * D + c * 8);
            }
        }
        asm volatile("cp.async.commit_group;" ::: "memory");
    };

    float acc[4][NT][4];
#pragma unroll
    for (int f = 0; f < 4; f++)
#pragma unroll
        for (int nf = 0; nf < NT; nf++)
#pragma unroll
            for (int r = 0; r < 4; r++) acc[f][nf][r] = 0.0f;

    // staged-buffer fragment bases (stride 20 words / 80B per row)
    int abase[4], bbase[NT];
#pragma unroll
    for (int f = 0; f < 4; f++) abase[f] = (wm + f * 16 + g) * 20 + t;
#pragma unroll
    for (int nf = 0; nf < NT; nf++) bbase[nf] = (wn + nf * 8 + g) * 20 + t;
    // resident-tile fragment bases: 128-word rows, word w stored at w^((r&7)<<2)
    const int xhi = (g & 6) << 2;              // swizzle bits 3-4
    const int xlo = t ^ ((g & 1) << 2);        // column bits 0-2 piece
    int tb0[4], tb1[4];
#pragma unroll
    for (int f = 0; f < 4; f++) {
        int rb = (wm + f * 16 + g) * 128;
        tb0[f] = rb + xlo;
        tb1[f] = rb + (xlo ^ 4);
    }

    stage(0, 0);
    stage(1, 1);

#pragma unroll 1
    for (int kc = 0; kc < 8; kc++) {
        const int b = kc & 1;
        if (kc < 7) asm volatile("cp.async.wait_group 1;" ::: "memory");
        else        asm volatile("cp.async.wait_group 0;" ::: "memory");
        __syncthreads();

#pragma unroll
        for (int kk = 0; kk < 2; kk++) {
            uint32_t a[4][4], bf[NT][2];
            if (MODE == 0) {
                const uint32_t* A_ = Ab[b];
                const int ko = kk * 8;
#pragma unroll
                for (int f = 0; f < 4; f++) {
                    a[f][0] = A_[abase[f] + ko];
                    a[f][1] = A_[abase[f] + 160 + ko];
                    a[f][2] = A_[abase[f] + ko + 4];
                    a[f][3] = A_[abase[f] + 160 + ko + 4];
                }
            } else {
                const uint32_t* A_ = (MODE == 1) ? Ht : (const uint32_t*)Gt;
                const int wofs = ((kc * 2 + kk) * 8) ^ xhi;
#pragma unroll
                for (int f = 0; f < 4; f++) {
                    a[f][0] = A_[tb0[f] + wofs];
                    a[f][1] = A_[tb0[f] + 1024 + wofs];
                    a[f][2] = A_[tb1[f] + wofs];
                    a[f][3] = A_[tb1[f] + 1024 + wofs];
                }
            }
            const uint32_t* B_ = Bb[b];
            const int ko = kk * 8;
#pragma unroll
            for (int nf = 0; nf < NT; nf++) {
                bf[nf][0] = B_[bbase[nf] + ko];
                bf[nf][1] = B_[bbase[nf] + ko + 4];
            }
#pragma unroll
            for (int f = 0; f < 4; f++)
#pragma unroll
                for (int nf = 0; nf < NT; nf++)
                    mma16(acc[f][nf], a[f], bf[nf]);
        }
        __syncthreads();
        if (kc + 2 < 8) stage(kc + 2, b);
    }
    // all warps past last sync => safe to overwrite G tile / write H tile

    // ------------------------------ epilogue --------------------------------
#pragma unroll
    for (int f = 0; f < 4; f++) {
        const int r = wm + f * 16 + g;           // local tile row (r&7 == g)
#pragma unroll
        for (int nf = 0; nf < NT; nf++) {
            const int nc = wn + nf * 8 + 2 * t;
            const int ws = (nc >> 1) ^ (g << 2); // swizzled word column
            float c0 = acc[f][nf][0], c1 = acc[f][nf][1];
            float c2 = acc[f][nf][2], c3 = acc[f][nf][3];

            if (MODE == 0) {
                float bv0 = sb1[nc], bv1 = sb1[nc + 1];
                Htw[r * 128 + ws]       = pk2(ftanh(c0 + bv0), ftanh(c1 + bv1));
                Htw[(r + 8) * 128 + ws] = pk2(ftanh(c2 + bv0), ftanh(c3 + bv1));
            } else if (MODE == 1) {
                float bv0 = sb2[nc], bv1 = sb2[nc + 1];
                float wv0 = swo[nc], wv1 = swo[nc + 1];
                float t0 = ftanh(c0 + bv0), t1 = ftanh(c1 + bv1);
                float t2 = ftanh(c2 + bv0), t3 = ftanh(c3 + bv1);
                Gt[r * 128 + ws]       = pk2(wv0 * (1.0f - t0 * t0),
                                             wv1 * (1.0f - t1 * t1));
                Gt[(r + 8) * 128 + ws] = pk2(wv0 * (1.0f - t2 * t2),
                                             wv1 * (1.0f - t3 * t3));
            } else if (MODE == 2) {
                float2 h0 = up2(Ht[r * 128 + ws]);
                float2 h1 = up2(Ht[(r + 8) * 128 + ws]);
                Gt[r * 128 + ws]       = pk2(c0 * (1.0f - h0.x * h0.x),
                                             c1 * (1.0f - h0.y * h0.y));
                Gt[(r + 8) * 128 + ws] = pk2(c2 * (1.0f - h1.x * h1.x),
                                             c3 * (1.0f - h1.y * h1.y));
            } else {
                const int grow = m0 + r;
                if (NT == 4 || nc < FD) {       // p kick: p -= 0.5*dt*dH[:, :FD]
                    float2* S0 = (float2*)(g_S + (size_t)grow * D + FD + nc);
                    float2* S1 = (float2*)(g_S + (size_t)(grow + 8) * D + FD + nc);
                    float2 p0 = *S0, p1 = *S1;
                    p0.x -= 0.5f * dtv * c0;  p0.y -= 0.5f * dtv * c1;
                    p1.x -= 0.5f * dtv * c2;  p1.y -= 0.5f * dtv * c3;
                    *S0 = p0;  *S1 = p1;
                    *(uint32_t*)(g_Sb + (size_t)grow * D + FD + nc)       = pk2(p0.x, p0.y);
                    *(uint32_t*)(g_Sb + (size_t)(grow + 8) * D + FD + nc) = pk2(p1.x, p1.y);
                } else {                         // q kick: q += dt*dH[:, FD:]
                    const int qc = nc - FD;
                    float2* S0 = (float2*)(g_S + (size_t)grow * D + qc);
                    float2* S1 = (float2*)(g_S + (size_t)(grow + 8) * D + qc);
                    float2 q0 = *S0, q1 = *S1;
                    q0.x += dtv * c0;  q0.y += dtv * c1;
                    q1.x += dtv * c2;  q1.y += dtv * c3;
                    *S0 = q0;  *S1 = q1;
                    *(uint32_t*)(g_Sb + (size_t)grow * D + qc)       = pk2(q0.x, q0.y);
                    *(uint32_t*)(g_Sb + (size_t)(grow + 8) * D + qc) = pk2(q1.x, q1.y);
                }
            }
        }
    }
    __syncthreads();   // tiles / g_Sb ready for next pass
}

// ------------------------------ fused kernel --------------------------------
__global__ void __launch_bounds__(256, 1)
fused_kernel(const float* __restrict__ b1, const float* __restrict__ b2,
             const float* __restrict__ wo) {
    extern __shared__ __align__(1024) char smem[];
    const uint32_t sbase = smem_u32(smem);
    const int tid = threadIdx.x;
    const int m0  = blockIdx.x * BM;

    ((float*)(smem + OFF_B1S))[tid] = b1[tid];
    ((float*)(smem + OFF_B2S))[tid] = b2[tid];
    ((float*)(smem + OFF_WO))[tid]  = wo[tid];
    __syncthreads();

    const float dtv = (m0 < BHALF) ? DT_MAG : -DT_MAG;

#pragma unroll 1
    for (int it = 0; it < 8; it++) {
        pass_gemm<0, 8>(smem, sbase, m0, dtv);
        pass_gemm<1, 8>(smem, sbase, m0, dtv);
        pass_gemm<2, 8>(smem, sbase, m0, dtv);
        if ((it & 1) == 0) pass_gemm<3, 8>(smem, sbase, m0, dtv);
        else               pass_gemm<4, 4>(smem, sbase, m0, dtv);
    }
}

// ---------------------------------------------------------------------------
extern "C" void kernel_launch(void* const* d_in, const int* in_sizes, int n_in,
                              void* d_out, int out_size) {
    const float* x    = (const float*)d_in[0];
    const float* W1   = (const float*)d_in[1];
    const float* b1   = (const float*)d_in[2];
    const float* W2   = (const float*)d_in[3];
    const float* b2   = (const float*)d_in[4];
    const float* Wout = (const float*)d_in[5];
    float* out = (float*)d_out;

    cudaFuncSetAttribute(fused_kernel,
                         cudaFuncAttributeMaxDynamicSharedMemorySize, SMEM_TOTAL);

    prep_kernel<<<D * D / 256, 256>>>(W1, W2);
    init_kernel<<<BHALF, 128>>>(x);
    fused_kernel<<<MTOT / BM, 256, SMEM_TOTAL>>>(b1, b2, Wout);
    final_kernel<<<BHALF, 128>>>(x, out);
}

// round 6
// speedup vs baseline: 5.9623x; 1.2157x over previous
#include <cuda_runtime.h>
#include <cuda_bf16.h>
#include <math.h>
#include <cstdint>

// ============================================================================
// BiDirectionalSymplecticLayer — fused persistent kernel, ldmatrix edition.
// Each CTA owns 128 rows and runs all 8 gradient evals locally; intermediates
// (H, G) live in swizzled smem tiles; weights stream L2->smem (k64 chunks,
// 144B-padded rows); all fragment loads via ldmatrix.m8n8.x4.
// ============================================================================

#define D       256
#define FD      128
#define MTOT    16384
#define BHALF   8192
#define DT_MAG  0.1f
#define BM      128

// smem layout (bytes)
#define OFF_H   0                       // H tile: 128 x 128 words, swizzled
#define OFF_G   65536                   // G tile (overlaid by A-staging in pass 1)
#define OFF_AB0 65536                   // A staging buf0: 128 x 144B
#define OFF_AB1 (65536 + 18432)
#define OFF_BB0 131072                  // B staging buf0: 256 x 144B
#define OFF_BB1 (131072 + 36864)
#define OFF_B1S 204800
#define OFF_B2S 205824
#define OFF_WO  206848
#define SMEM_TOTAL 207872

__device__ float         g_S [MTOT * D];
__device__ __nv_bfloat16 g_Sb[MTOT * D];
__device__ __nv_bfloat16 g_W1b [D * D];    // W1  [n][k]
__device__ __nv_bfloat16 g_W2b [D * D];    // W2  [n][k]
__device__ __nv_bfloat16 g_W1Tb[D * D];    // W1^T [n][k]
__device__ __nv_bfloat16 g_W2Tb[D * D];    // W2^T [n][k]

// ------------------------------- helpers ------------------------------------
__device__ __forceinline__ void cpa16(uint32_t dst, const void* src) {
    asm volatile("cp.async.cg.shared.global [%0], [%1], 16;"
                 :: "r"(dst), "l"(src) : "memory");
}
__device__ __forceinline__ uint32_t smem_u32(const void* p) {
    uint32_t r;
    asm("{ .reg .u64 t; cvta.to.shared.u64 t, %1; cvt.u32.u64 %0, t; }"
        : "=r"(r) : "l"(p));
    return r;
}
__device__ __forceinline__ void mma16(float* c, const uint32_t* a, const uint32_t* b) {
    asm volatile(
        "mma.sync.aligned.m16n8k16.row.col.f32.bf16.bf16.f32 "
        "{%0,%1,%2,%3}, {%4,%5,%6,%7}, {%8,%9}, {%0,%1,%2,%3};"
        : "+f"(c[0]), "+f"(c[1]), "+f"(c[2]), "+f"(c[3])
        : "r"(a[0]), "r"(a[1]), "r"(a[2]), "r"(a[3]), "r"(b[0]), "r"(b[1]));
}
#define LDMX4(r, addr) \
    asm volatile("ldmatrix.sync.aligned.m8n8.x4.shared.b16 {%0,%1,%2,%3}, [%4];" \
                 : "=r"((r)[0]), "=r"((r)[1]), "=r"((r)[2]), "=r"((r)[3]) \
                 : "r"(addr))
__device__ __forceinline__ uint32_t pk2(float x, float y) {
    __nv_bfloat162 h = __floats2bfloat162_rn(x, y);
    return *reinterpret_cast<uint32_t*>(&h);
}
__device__ __forceinline__ float2 up2(uint32_t u) {
    __nv_bfloat162 h = *reinterpret_cast<__nv_bfloat162*>(&u);
    return make_float2(__bfloat162float(h.x), __bfloat162float(h.y));
}
__device__ __forceinline__ float ftanh(float x) {
    float e;
    asm("ex2.approx.f32 %0, %1;" : "=f"(e) : "f"(x * 2.885390082f));
    float r;
    asm("rcp.approx.f32 %0, %1;" : "=f"(r) : "f"(e + 1.0f));
    return 1.0f - 2.0f * r;
}

// --------------------------- prologue kernels -------------------------------
__global__ void prep_kernel(const float* __restrict__ W1,
                            const float* __restrict__ W2) {
    int idx = blockIdx.x * blockDim.x + threadIdx.x;
    int r = idx >> 8, c = idx & 255;
    __nv_bfloat16 v1 = __float2bfloat16(W1[idx]);
    __nv_bfloat16 v2 = __float2bfloat16(W2[idx]);
    g_W1b[idx] = v1;
    g_W2b[idx] = v2;
    g_W1Tb[c * D + r] = v1;
    g_W2Tb[c * D + r] = v2;
}

__global__ void init_kernel(const float* __restrict__ x) {
    int b = blockIdx.x, f = threadIdx.x;
    size_t xb = (size_t)b * 64 * 128;
    float xm  = x[xb + 32 * 128 + f];
    float xm1 = x[xb + 31 * 128 + f];
    float q = xm, p = xm - xm1;
    size_t o0 = (size_t)b * D, o1 = (size_t)(BHALF + b) * D;
    g_S[o0 + f] = q;       g_S[o0 + FD + f] = p;
    g_S[o1 + f] = q;       g_S[o1 + FD + f] = p;
    __nv_bfloat16 qb = __float2bfloat16(q), pb = __float2bfloat16(p);
    g_Sb[o0 + f] = qb;     g_Sb[o0 + FD + f] = pb;
    g_Sb[o1 + f] = qb;     g_Sb[o1 + FD + f] = pb;
}

__global__ void final_kernel(const float* __restrict__ x,
                             float* __restrict__ out) {
    int b = blockIdx.x, f = threadIdx.x;
    size_t xb = (size_t)b * 64 * 128;
    float xm  = x[xb + 32 * 128 + f];
    float xm1 = x[xb + 31 * 128 + f];
    size_t ob = (size_t)b * 768;
    size_t sf = (size_t)b * D;
    size_t sb = (size_t)(BHALF + b) * D;
    out[ob + 0 * FD + f] = g_S[sb + f];
    out[ob + 1 * FD + f] = g_S[sb + FD + f];
    out[ob + 2 * FD + f] = xm;
    out[ob + 3 * FD + f] = xm - xm1;
    out[ob + 4 * FD + f] = g_S[sf + f];
    out[ob + 5 * FD + f] = g_S[sf + FD + f];
}

// ------------------------------ fused pass ----------------------------------
//  MODE 0: A = staged g_Sb, B = g_W1Tb -> H = tanh(acc + b1)
//  MODE 1: A = H tile,      B = g_W2Tb -> G = wout*(1 - tanh(acc+b2)^2)
//  MODE 2: A = G tile,      B = g_W2b  -> G = acc*(1 - H^2)
//  MODE 3: A = G tile,      B = g_W1b  -> full kick (NT=8)
//  MODE 4: A = G tile,      B = g_W1b  -> half kick (NT=4)
template <int MODE, int NT>
__device__ __forceinline__ void pass_gemm(char* smem, uint32_t sbase,
                                          int m0, float dtv) {
    const int tid  = threadIdx.x;
    const int wid  = tid >> 5;
    const int lane = tid & 31;
    const int g    = lane >> 2;
    const int t    = lane & 3;
    const int wm   = (wid & 1) * 64;
    const int wn   = (wid >> 1) * (NT * 8);
    const int NTOT = NT * 32;

    const uint32_t* Ht  = (const uint32_t*)(smem + OFF_H);
    uint32_t*       Htw = (uint32_t*)(smem + OFF_H);
    uint32_t*       Gt  = (uint32_t*)(smem + OFF_G);
    const float* sb1 = (const float*)(smem + OFF_B1S);
    const float* sb2 = (const float*)(smem + OFF_B2S);
    const float* swo = (const float*)(smem + OFF_WO);

    const __nv_bfloat16* Bsrc =
        (MODE == 0) ? g_W1Tb : (MODE == 1) ? g_W2Tb :
        (MODE == 2) ? g_W2b : g_W1b;

    // ---- stage one k64 chunk of B (and A for MODE 0) into 144B-stride bufs
    auto stage = [&](int kc, int b) {
        const __nv_bfloat16* Bg = Bsrc + kc * 64;
        const uint32_t bdst = sbase + (b ? OFF_BB1 : OFF_BB0);
#pragma unroll
        for (int i = 0; i < NTOT / 32; i++) {
            int idx = tid + (i << 8);
            int row = idx >> 3, c = idx & 7;
            cpa16(bdst + row * 144 + c * 16, Bg + (size_t)row * D + c * 8);
        }
        if (MODE == 0) {
            const __nv_bfloat16* Ag = g_Sb + (size_t)m0 * D + kc * 64;
            const uint32_t adst = sbase + (b ? OFF_AB1 : OFF_AB0);
#pragma unroll
            for (int i = 0; i < 4; i++) {
                int idx = tid + (i << 8);
                int row = idx >> 3, c = idx & 7;
                cpa16(adst + row * 144 + c * 16, Ag + (size_t)row * D + c * 8);
            }
        }
        asm volatile("cp.async.commit_group;" ::: "memory");
    };

    float acc[4][NT][4];
#pragma unroll
    for (int f = 0; f < 4; f++)
#pragma unroll
        for (int nf = 0; nf < NT; nf++)
#pragma unroll
            for (int r = 0; r < 4; r++) acc[f][nf][r] = 0.0f;

    // ldmatrix per-lane bases
    const uint32_t aStOff =
        (uint32_t)(wm + (lane & 15)) * 144 + ((lane >> 4) << 4);
    const uint32_t bStOff =
        (uint32_t)(wn + ((lane >> 4) << 3) + (lane & 7)) * 144 +
        (((lane >> 3) & 1) << 4);
    const int hi4w = (lane >> 4) << 2;          // 16B-half, in words
    const int row7 = (lane & 7) << 2;           // tile swizzle bits
    uint32_t rrb[4];
#pragma unroll
    for (int f = 0; f < 4; f++)
        rrb[f] = sbase + ((MODE == 1) ? OFF_H : OFF_G) +
                 (uint32_t)(wm + f * 16 + (lane & 15)) * 512;

    stage(0, 0);
    stage(1, 1);

#pragma unroll 1
    for (int kc = 0; kc < 4; kc++) {
        const int b = kc & 1;
        if (kc < 3) asm volatile("cp.async.wait_group 1;" ::: "memory");
        else        asm volatile("cp.async.wait_group 0;" ::: "memory");
        __syncthreads();

        const uint32_t aSt = sbase + (b ? OFF_AB1 : OFF_AB0) + aStOff;
        const uint32_t bSt = sbase + (b ? OFF_BB1 : OFF_BB0) + bStOff;

#pragma unroll
        for (int kk = 0; kk < 4; kk++) {
            const int kg = kc * 4 + kk;
            uint32_t a[4][4], bb[NT][2];
            if (MODE == 0) {
                const uint32_t ab = aSt + kk * 32;
#pragma unroll
                for (int f = 0; f < 4; f++) LDMX4(a[f], ab + f * 2304);
            } else {
                const uint32_t s4 = (uint32_t)((((kg << 3) + hi4w) ^ row7) << 2);
#pragma unroll
                for (int f = 0; f < 4; f++) LDMX4(a[f], rrb[f] + s4);
            }
#pragma unroll
            for (int j = 0; j < NT / 2; j++) {
                uint32_t r[4];
                LDMX4(r, bSt + j * 2304 + kk * 32);
                bb[2*j][0] = r[0];  bb[2*j][1] = r[1];
                bb[2*j+1][0] = r[2];  bb[2*j+1][1] = r[3];
            }
#pragma unroll
            for (int f = 0; f < 4; f++)
#pragma unroll
                for (int nf = 0; nf < NT; nf++)
                    mma16(acc[f][nf], a[f], bb[nf]);
        }
        __syncthreads();
        if (kc + 2 < 4) stage(kc + 2, b);
    }

    // ------------------------------ epilogue --------------------------------
#pragma unroll
    for (int f = 0; f < 4; f++) {
        const int r = wm + f * 16 + g;           // local row; r&7 == g
#pragma unroll
        for (int nf = 0; nf < NT; nf++) {
            const int nc = wn + nf * 8 + 2 * t;
            const int ws = (nc >> 1) ^ (g << 2);
            float c0 = acc[f][nf][0], c1 = acc[f][nf][1];
            float c2 = acc[f][nf][2], c3 = acc[f][nf][3];

            if (MODE == 0) {
                float bv0 = sb1[nc], bv1 = sb1[nc + 1];
                Htw[r * 128 + ws]       = pk2(ftanh(c0 + bv0), ftanh(c1 + bv1));
                Htw[(r + 8) * 128 + ws] = pk2(ftanh(c2 + bv0), ftanh(c3 + bv1));
            } else if (MODE == 1) {
                float bv0 = sb2[nc], bv1 = sb2[nc + 1];
                float wv0 = swo[nc], wv1 = swo[nc + 1];
                float t0 = ftanh(c0 + bv0), t1 = ftanh(c1 + bv1);
                float t2 = ftanh(c2 + bv0), t3 = ftanh(c3 + bv1);
                Gt[r * 128 + ws]       = pk2(wv0 * (1.0f - t0 * t0),
                                             wv1 * (1.0f - t1 * t1));
                Gt[(r + 8) * 128 + ws] = pk2(wv0 * (1.0f - t2 * t2),
                                             wv1 * (1.0f - t3 * t3));
            } else if (MODE == 2) {
                float2 h0 = up2(Ht[r * 128 + ws]);
                float2 h1 = up2(Ht[(r + 8) * 128 + ws]);
                Gt[r * 128 + ws]       = pk2(c0 * (1.0f - h0.x * h0.x),
                                             c1 * (1.0f - h0.y * h0.y));
                Gt[(r + 8) * 128 + ws] = pk2(c2 * (1.0f - h1.x * h1.x),
                                             c3 * (1.0f - h1.y * h1.y));
            } else {
                const int grow = m0 + r;
                if (NT == 4 || nc < FD) {        // p -= 0.5*dt*dH[:, :FD]
                    float2* S0 = (float2*)(g_S + (size_t)grow * D + FD + nc);
                    float2* S1 = (float2*)(g_S + (size_t)(grow + 8) * D + FD + nc);
                    float2 p0 = *S0, p1 = *S1;
                    p0.x -= 0.5f * dtv * c0;  p0.y -= 0.5f * dtv * c1;
                    p1.x -= 0.5f * dtv * c2;  p1.y -= 0.5f * dtv * c3;
                    *S0 = p0;  *S1 = p1;
                    *(uint32_t*)(g_Sb + (size_t)grow * D + FD + nc)       = pk2(p0.x, p0.y);
                    *(uint32_t*)(g_Sb + (size_t)(grow + 8) * D + FD + nc) = pk2(p1.x, p1.y);
                } else {                          // q += dt*dH[:, FD:]
                    const int qc = nc - FD;
                    float2* S0 = (float2*)(g_S + (size_t)grow * D + qc);
                    float2* S1 = (float2*)(g_S + (size_t)(grow + 8) * D + qc);
                    float2 q0 = *S0, q1 = *S1;
                    q0.x += dtv * c0;  q0.y += dtv * c1;
                    q1.x += dtv * c2;  q1.y += dtv * c3;
                    *S0 = q0;  *S1 = q1;
                    *(uint32_t*)(g_Sb + (size_t)grow * D + qc)       = pk2(q0.x, q0.y);
                    *(uint32_t*)(g_Sb + (size_t)(grow + 8) * D + qc) = pk2(q1.x, q1.y);
                }
            }
        }
    }
    // no trailing barrier: next pass's post-wait __syncthreads orders tile
    // writes before any tile read; staged buffers are only touched after all
    // warps passed the kc=3 post-compute barrier above.
}

// ------------------------------ fused kernel --------------------------------
__global__ void __launch_bounds__(256, 1)
fused_kernel(const float* __restrict__ b1, const float* __restrict__ b2,
             const float* __restrict__ wo) {
    extern __shared__ __align__(1024) char smem[];
    const uint32_t sbase = smem_u32(smem);
    const int tid = threadIdx.x;
    const int m0  = blockIdx.x * BM;

    ((float*)(smem + OFF_B1S))[tid] = b1[tid];
    ((float*)(smem + OFF_B2S))[tid] = b2[tid];
    ((float*)(smem + OFF_WO))[tid]  = wo[tid];
    __syncthreads();

    const float dtv = (m0 < BHALF) ? DT_MAG : -DT_MAG;

#pragma unroll 1
    for (int it = 0; it < 8; it++) {
        pass_gemm<0, 8>(smem, sbase, m0, dtv);
        pass_gemm<1, 8>(smem, sbase, m0, dtv);
        pass_gemm<2, 8>(smem, sbase, m0, dtv);
        if ((it & 1) == 0) pass_gemm<3, 8>(smem, sbase, m0, dtv);
        else               pass_gemm<4, 4>(smem, sbase, m0, dtv);
    }
}

// ---------------------------------------------------------------------------
extern "C" void kernel_launch(void* const* d_in, const int* in_sizes, int n_in,
                              void* d_out, int out_size) {
    const float* x    = (const float*)d_in[0];
    const float* W1   = (const float*)d_in[1];
    const float* b1   = (const float*)d_in[2];
    const float* W2   = (const float*)d_in[3];
    const float* b2   = (const float*)d_in[4];
    const float* Wout = (const float*)d_in[5];
    float* out = (float*)d_out;

    cudaFuncSetAttribute(fused_kernel,
                         cudaFuncAttributeMaxDynamicSharedMemorySize, SMEM_TOTAL);

    prep_kernel<<<D * D / 256, 256>>>(W1, W2);
    init_kernel<<<BHALF, 128>>>(x);
    fused_kernel<<<MTOT / BM, 256, SMEM_TOTAL>>>(b1, b2, Wout);
    final_kernel<<<BHALF, 128>>>(x, out);
}

// round 7
// speedup vs baseline: 6.2260x; 1.0442x over previous
#include <cuda_runtime.h>
#include <cuda_bf16.h>
#include <math.h>
#include <cstdint>

// ============================================================================
// BiDirectionalSymplecticLayer — fused persistent kernel, 16-warp edition.
// Each CTA owns 128 rows, runs all 8 gradient evals locally. Intermediates
// (H, G) in swizzled smem tiles; weights stream L2->smem (k64 chunks, 144B
// rows); ldmatrix.m8n8.x4 fragment loads; 512 threads (4 warps/SMSP) so the
// arbiter can hide LDSM/barrier/epilogue latency. Warp tile 32x64.
// ============================================================================

#define D       256
#define FD      128
#define MTOT    16384
#define BHALF   8192
#define DT_MAG  0.1f
#define BM      128
#define NTH     512

// smem layout (bytes)
#define OFF_H   0                       // H tile: 128 x 128 words, swizzled
#define OFF_G   65536                   // G tile (overlaid by A-staging pass 1)
#define OFF_AB0 65536                   // A staging buf0: 128 x 144B
#define OFF_AB1 (65536 + 18432)
#define OFF_BB0 131072                  // B staging buf0: 256 x 144B
#define OFF_BB1 (131072 + 36864)
#define OFF_B1S 204800
#define OFF_B2S 205824
#define OFF_WO  206848
#define SMEM_TOTAL 207872

__device__ float         g_S [MTOT * D];
__device__ __nv_bfloat16 g_Sb[MTOT * D];
__device__ __nv_bfloat16 g_W1b [D * D];    // W1  [n][k]
__device__ __nv_bfloat16 g_W2b [D * D];    // W2  [n][k]
__device__ __nv_bfloat16 g_W1Tb[D * D];    // W1^T [n][k]
__device__ __nv_bfloat16 g_W2Tb[D * D];    // W2^T [n][k]

// ------------------------------- helpers ------------------------------------
__device__ __forceinline__ void cpa16(uint32_t dst, const void* src) {
    asm volatile("cp.async.cg.shared.global [%0], [%1], 16;"
                 :: "r"(dst), "l"(src) : "memory");
}
__device__ __forceinline__ uint32_t smem_u32(const void* p) {
    uint32_t r;
    asm("{ .reg .u64 t; cvta.to.shared.u64 t, %1; cvt.u32.u64 %0, t; }"
        : "=r"(r) : "l"(p));
    return r;
}
__device__ __forceinline__ void mma16(float* c, const uint32_t* a, const uint32_t* b) {
    asm volatile(
        "mma.sync.aligned.m16n8k16.row.col.f32.bf16.bf16.f32 "
        "{%0,%1,%2,%3}, {%4,%5,%6,%7}, {%8,%9}, {%0,%1,%2,%3};"
        : "+f"(c[0]), "+f"(c[1]), "+f"(c[2]), "+f"(c[3])
        : "r"(a[0]), "r"(a[1]), "r"(a[2]), "r"(a[3]), "r"(b[0]), "r"(b[1]));
}
#define LDMX4(r, addr) \
    asm volatile("ldmatrix.sync.aligned.m8n8.x4.shared.b16 {%0,%1,%2,%3}, [%4];" \
                 : "=r"((r)[0]), "=r"((r)[1]), "=r"((r)[2]), "=r"((r)[3]) \
                 : "r"(addr))
__device__ __forceinline__ uint32_t pk2(float x, float y) {
    __nv_bfloat162 h = __floats2bfloat162_rn(x, y);
    return *reinterpret_cast<uint32_t*>(&h);
}
__device__ __forceinline__ float2 up2(uint32_t u) {
    __nv_bfloat162 h = *reinterpret_cast<__nv_bfloat162*>(&u);
    return make_float2(__bfloat162float(h.x), __bfloat162float(h.y));
}
__device__ __forceinline__ float ftanh(float x) {
    float e;
    asm("ex2.approx.f32 %0, %1;" : "=f"(e) : "f"(x * 2.885390082f));
    float r;
    asm("rcp.approx.f32 %0, %1;" : "=f"(r) : "f"(e + 1.0f));
    return 1.0f - 2.0f * r;
}

// --------------------------- prologue kernels -------------------------------
__global__ void prep_kernel(const float* __restrict__ W1,
                            const float* __restrict__ W2) {
    int idx = blockIdx.x * blockDim.x + threadIdx.x;
    int r = idx >> 8, c = idx & 255;
    __nv_bfloat16 v1 = __float2bfloat16(W1[idx]);
    __nv_bfloat16 v2 = __float2bfloat16(W2[idx]);
    g_W1b[idx] = v1;
    g_W2b[idx] = v2;
    g_W1Tb[c * D + r] = v1;
    g_W2Tb[c * D + r] = v2;
}

__global__ void init_kernel(const float* __restrict__ x) {
    int b = blockIdx.x, f = threadIdx.x;
    size_t xb = (size_t)b * 64 * 128;
    float xm  = x[xb + 32 * 128 + f];
    float xm1 = x[xb + 31 * 128 + f];
    float q = xm, p = xm - xm1;
    size_t o0 = (size_t)b * D, o1 = (size_t)(BHALF + b) * D;
    g_S[o0 + f] = q;       g_S[o0 + FD + f] = p;
    g_S[o1 + f] = q;       g_S[o1 + FD + f] = p;
    __nv_bfloat16 qb = __float2bfloat16(q), pb = __float2bfloat16(p);
    g_Sb[o0 + f] = qb;     g_Sb[o0 + FD + f] = pb;
    g_Sb[o1 + f] = qb;     g_Sb[o1 + FD + f] = pb;
}

__global__ void final_kernel(const float* __restrict__ x,
                             float* __restrict__ out) {
    int b = blockIdx.x, f = threadIdx.x;
    size_t xb = (size_t)b * 64 * 128;
    float xm  = x[xb + 32 * 128 + f];
    float xm1 = x[xb + 31 * 128 + f];
    size_t ob = (size_t)b * 768;
    size_t sf = (size_t)b * D;
    size_t sb = (size_t)(BHALF + b) * D;
    out[ob + 0 * FD + f] = g_S[sb + f];
    out[ob + 1 * FD + f] = g_S[sb + FD + f];
    out[ob + 2 * FD + f] = xm;
    out[ob + 3 * FD + f] = xm - xm1;
    out[ob + 4 * FD + f] = g_S[sf + f];
    out[ob + 5 * FD + f] = g_S[sf + FD + f];
}

// ------------------------------ fused pass ----------------------------------
//  MODE 0: A = staged g_Sb, B = g_W1Tb -> H = tanh(acc + b1)
//  MODE 1: A = H tile,      B = g_W2Tb -> G = wout*(1 - tanh(acc+b2)^2)
//  MODE 2: A = G tile,      B = g_W2b  -> G = acc*(1 - H^2)
//  MODE 3: A = G tile,      B = g_W1b  -> full kick (NT=8)
//  MODE 4: A = G tile,      B = g_W1b  -> half kick (NT=4)
// 16 warps: wm = (wid&3)*32 (4 m-splits), wn = (wid>>2)*(NT*8) (4 n-splits).
template <int MODE, int NT>
__device__ __forceinline__ void pass_gemm(char* smem, uint32_t sbase,
                                          int m0, float dtv) {
    const int tid  = threadIdx.x;
    const int wid  = tid >> 5;
    const int lane = tid & 31;
    const int g    = lane >> 2;
    const int t    = lane & 3;
    const int wm   = (wid & 3) * 32;
    const int wn   = (wid >> 2) * (NT * 8);
    const int NTOT = NT * 32;

    const uint32_t* Ht  = (const uint32_t*)(smem + OFF_H);
    uint32_t*       Htw = (uint32_t*)(smem + OFF_H);
    uint32_t*       Gt  = (uint32_t*)(smem + OFF_G);
    const float* sb1 = (const float*)(smem + OFF_B1S);
    const float* sb2 = (const float*)(smem + OFF_B2S);
    const float* swo = (const float*)(smem + OFF_WO);

    const __nv_bfloat16* Bsrc =
        (MODE == 0) ? g_W1Tb : (MODE == 1) ? g_W2Tb :
        (MODE == 2) ? g_W2b : g_W1b;

    // ---- stage one k64 chunk of B (and A for MODE 0); 144B row stride
    auto stage = [&](int kc, int b) {
        const __nv_bfloat16* Bg = Bsrc + kc * 64;
        const uint32_t bdst = sbase + (b ? OFF_BB1 : OFF_BB0);
#pragma unroll
        for (int i = 0; i < NTOT / 64; i++) {     // NTOT rows x 8 xfers / 512
            int idx = tid + (i << 9);
            int row = idx >> 3, c = idx & 7;
            cpa16(bdst + row * 144 + c * 16, Bg + (size_t)row * D + c * 8);
        }
        if (MODE == 0) {
            const __nv_bfloat16* Ag = g_Sb + (size_t)m0 * D + kc * 64;
            const uint32_t adst = sbase + (b ? OFF_AB1 : OFF_AB0);
#pragma unroll
            for (int i = 0; i < 2; i++) {         // 1024 xfers / 512 threads
                int idx = tid + (i << 9);
                int row = idx >> 3, c = idx & 7;
                cpa16(adst + row * 144 + c * 16, Ag + (size_t)row * D + c * 8);
            }
        }
        asm volatile("cp.async.commit_group;" ::: "memory");
    };

    float acc[2][NT][4];
#pragma unroll
    for (int f = 0; f < 2; f++)
#pragma unroll
        for (int nf = 0; nf < NT; nf++)
#pragma unroll
            for (int r = 0; r < 4; r++) acc[f][nf][r] = 0.0f;

    // ldmatrix per-lane bases
    const uint32_t aStOff =
        (uint32_t)(wm + (lane & 15)) * 144 + ((lane >> 4) << 4);
    const uint32_t bStOff =
        (uint32_t)(wn + ((lane >> 4) << 3) + (lane & 7)) * 144 +
        (((lane >> 3) & 1) << 4);
    const int hi4w = (lane >> 4) << 2;          // 16B-half, in words
    const int row7 = (lane & 7) << 2;           // tile swizzle bits
    uint32_t rrb[2];
#pragma unroll
    for (int f = 0; f < 2; f++)
        rrb[f] = sbase + ((MODE == 1) ? OFF_H : OFF_G) +
                 (uint32_t)(wm + f * 16 + (lane & 15)) * 512;

    stage(0, 0);
    stage(1, 1);

#pragma unroll 1
    for (int kc = 0; kc < 4; kc++) {
        const int b = kc & 1;
        if (kc < 3) asm volatile("cp.async.wait_group 1;" ::: "memory");
        else        asm volatile("cp.async.wait_group 0;" ::: "memory");
        __syncthreads();

        const uint32_t aSt = sbase + (b ? OFF_AB1 : OFF_AB0) + aStOff;
        const uint32_t bSt = sbase + (b ? OFF_BB1 : OFF_BB0) + bStOff;

#pragma unroll
        for (int kk = 0; kk < 4; kk++) {
            const int kg = kc * 4 + kk;
            uint32_t a[2][4], bb[NT][2];
            if (MODE == 0) {
                const uint32_t ab = aSt + kk * 32;
#pragma unroll
                for (int f = 0; f < 2; f++) LDMX4(a[f], ab + f * 2304);
            } else {
                const uint32_t s4 = (uint32_t)((((kg << 3) + hi4w) ^ row7) << 2);
#pragma unroll
                for (int f = 0; f < 2; f++) LDMX4(a[f], rrb[f] + s4);
            }
#pragma unroll
            for (int j = 0; j < NT / 2; j++) {
                uint32_t r[4];
                LDMX4(r, bSt + j * 2304 + kk * 32);
                bb[2*j][0]   = r[0];  bb[2*j][1]   = r[1];
                bb[2*j+1][0] = r[2];  bb[2*j+1][1] = r[3];
            }
#pragma unroll
            for (int f = 0; f < 2; f++)
#pragma unroll
                for (int nf = 0; nf < NT; nf++)
                    mma16(acc[f][nf], a[f], bb[nf]);
        }
        __syncthreads();
        if (kc + 2 < 4) stage(kc + 2, b);
    }

    // ------------------------------ epilogue --------------------------------
#pragma unroll
    for (int f = 0; f < 2; f++) {
        const int r = wm + f * 16 + g;           // local row; r&7 == g
#pragma unroll
        for (int nf = 0; nf < NT; nf++) {
            const int nc = wn + nf * 8 + 2 * t;
            const int ws = (nc >> 1) ^ (g << 2);
            float c0 = acc[f][nf][0], c1 = acc[f][nf][1];
            float c2 = acc[f][nf][2], c3 = acc[f][nf][3];

            if (MODE == 0) {
                float bv0 = sb1[nc], bv1 = sb1[nc + 1];
                Htw[r * 128 + ws]       = pk2(ftanh(c0 + bv0), ftanh(c1 + bv1));
                Htw[(r + 8) * 128 + ws] = pk2(ftanh(c2 + bv0), ftanh(c3 + bv1));
            } else if (MODE == 1) {
                float bv0 = sb2[nc], bv1 = sb2[nc + 1];
                float wv0 = swo[nc], wv1 = swo[nc + 1];
                float t0 = ftanh(c0 + bv0), t1 = ftanh(c1 + bv1);
                float t2 = ftanh(c2 + bv0), t3 = ftanh(c3 + bv1);
                Gt[r * 128 + ws]       = pk2(wv0 * (1.0f - t0 * t0),
                                             wv1 * (1.0f - t1 * t1));
                Gt[(r + 8) * 128 + ws] = pk2(wv0 * (1.0f - t2 * t2),
                                             wv1 * (1.0f - t3 * t3));
            } else if (MODE == 2) {
                float2 h0 = up2(Ht[r * 128 + ws]);
                float2 h1 = up2(Ht[(r + 8) * 128 + ws]);
                Gt[r * 128 + ws]       = pk2(c0 * (1.0f - h0.x * h0.x),
                                             c1 * (1.0f - h0.y * h0.y));
                Gt[(r + 8) * 128 + ws] = pk2(c2 * (1.0f - h1.x * h1.x),
                                             c3 * (1.0f - h1.y * h1.y));
            } else {
                const int grow = m0 + r;
                if (NT == 4 || nc < FD) {        // p -= 0.5*dt*dH[:, :FD]
                    float2* S0 = (float2*)(g_S + (size_t)grow * D + FD + nc);
                    float2* S1 = (float2*)(g_S + (size_t)(grow + 8) * D + FD + nc);
                    float2 p0 = *S0, p1 = *S1;
                    p0.x -= 0.5f * dtv * c0;  p0.y -= 0.5f * dtv * c1;
                    p1.x -= 0.5f * dtv * c2;  p1.y -= 0.5f * dtv * c3;
                    *S0 = p0;  *S1 = p1;
                    *(uint32_t*)(g_Sb + (size_t)grow * D + FD + nc)       = pk2(p0.x, p0.y);
                    *(uint32_t*)(g_Sb + (size_t)(grow + 8) * D + FD + nc) = pk2(p1.x, p1.y);
                } else {                          // q += dt*dH[:, FD:]
                    const int qc = nc - FD;
                    float2* S0 = (float2*)(g_S + (size_t)grow * D + qc);
                    float2* S1 = (float2*)(g_S + (size_t)(grow + 8) * D + qc);
                    float2 q0 = *S0, q1 = *S1;
                    q0.x += dtv * c0;  q0.y += dtv * c1;
                    q1.x += dtv * c2;  q1.y += dtv * c3;
                    *S0 = q0;  *S1 = q1;
                    *(uint32_t*)(g_Sb + (size_t)grow * D + qc)       = pk2(q0.x, q0.y);
                    *(uint32_t*)(g_Sb + (size_t)(grow + 8) * D + qc) = pk2(q1.x, q1.y);
                }
            }
        }
    }
    // no trailing barrier: the next pass's post-wait __syncthreads orders
    // tile writes before any tile read; staged buffers are only reused after
    // all warps passed the kc=3 post-compute barrier above.
}

// ------------------------------ fused kernel --------------------------------
__global__ void __launch_bounds__(NTH, 1)
fused_kernel(const float* __restrict__ b1, const float* __restrict__ b2,
             const float* __restrict__ wo) {
    extern __shared__ __align__(1024) char smem[];
    const uint32_t sbase = smem_u32(smem);
    const int tid = threadIdx.x;
    const int m0  = blockIdx.x * BM;

    if (tid < 256) {
        ((float*)(smem + OFF_B1S))[tid] = b1[tid];
        ((float*)(smem + OFF_B2S))[tid] = b2[tid];
        ((float*)(smem + OFF_WO))[tid]  = wo[tid];
    }
    __syncthreads();

    const float dtv = (m0 < BHALF) ? DT_MAG : -DT_MAG;

#pragma unroll 1
    for (int it = 0; it < 8; it++) {
        pass_gemm<0, 8>(smem, sbase, m0, dtv);
        pass_gemm<1, 8>(smem, sbase, m0, dtv);
        pass_gemm<2, 8>(smem, sbase, m0, dtv);
        if ((it & 1) == 0) pass_gemm<3, 8>(smem, sbase, m0, dtv);
        else               pass_gemm<4, 4>(smem, sbase, m0, dtv);
    }
}

// ---------------------------------------------------------------------------
extern "C" void kernel_launch(void* const* d_in, const int* in_sizes, int n_in,
                              void* d_out, int out_size) {
    const float* x    = (const float*)d_in[0];
    const float* W1   = (const float*)d_in[1];
    const float* b1   = (const float*)d_in[2];
    const float* W2   = (const float*)d_in[3];
    const float* b2   = (const float*)d_in[4];
    const float* Wout = (const float*)d_in[5];
    float* out = (float*)d_out;

    cudaFuncSetAttribute(fused_kernel,
                         cudaFuncAttributeMaxDynamicSharedMemorySize, SMEM_TOTAL);

    prep_kernel<<<D * D / 256, 256>>>(W1, W2);
    init_kernel<<<BHALF, 128>>>(x);
    fused_kernel<<<MTOT / BM, NTH, SMEM_TOTAL>>>(b1, b2, Wout);
    final_kernel<<<BHALF, 128>>>(x, out);
}